// round 12
// baseline (speedup 1.0000x reference)
#include <cuda_runtime.h>
#include <cuda_bf16.h>
#include <stdint.h>

#define B_    16
#define T_    8
#define NIMG  128
#define CIN   128
#define COUT  256
#define HIN   56
#define P     28
#define PP    784
#define BN_EPS 1e-5f

#define NKS   456          // conv2: 432 + 24 ds k-steps

// ---------------- device scratch ----------------
__device__ float g_u1[(size_t)NIMG * COUT * PP];
__device__ float g_s1[(size_t)NIMG * COUT * PP];
__device__ float g_u2[(size_t)NIMG * COUT * PP];
__device__ float g_scale[3 * COUT];
__device__ float g_bias[3 * COUT];
__device__ float g_b2d[COUT];
// B fragments: [kstep][ng 8][lane 32][j 4] uint2 (uint2 = 2x bf16-pair along k)
__device__ __align__(16) uint32_t g_wpack[(size_t)NKS * 2048];

// ---------------- helpers ----------------
__device__ __forceinline__ uint32_t smem_u32(const void* p){
    uint32_t a;
    asm("{ .reg .u64 t; cvta.to.shared.u64 t, %1; cvt.u32.u64 %0, t; }" : "=r"(a) : "l"(p));
    return a;
}
__device__ __forceinline__ uint32_t pk_bf16(float a, float b){
    return (uint32_t)__bfloat16_as_ushort(__float2bfloat16(a))
         | ((uint32_t)__bfloat16_as_ushort(__float2bfloat16(b)) << 16);
}
__device__ __forceinline__ float split_term(float w, int s){
    float a = __bfloat162float(__float2bfloat16(w));
    if (s == 0) return a;
    float r = w - a;
    float b = __bfloat162float(__float2bfloat16(r));
    if (s == 1) return b;
    return r - b;
}

#define LDM4(a, ad) asm volatile( \
    "ldmatrix.sync.aligned.m8n8.x4.shared.b16 {%0,%1,%2,%3}, [%4];" \
    : "=r"((a)[0]), "=r"((a)[1]), "=r"((a)[2]), "=r"((a)[3]) : "r"(ad))

#define MMA16816(c, a, b0, b1) asm volatile( \
    "mma.sync.aligned.m16n8k16.row.col.f32.bf16.bf16.f32 " \
    "{%0,%1,%2,%3}, {%4,%5,%6,%7}, {%8,%9}, {%0,%1,%2,%3};" \
    : "+f"((c)[0]), "+f"((c)[1]), "+f"((c)[2]), "+f"((c)[3]) \
    : "r"((a)[0]), "r"((a)[1]), "r"((a)[2]), "r"((a)[3]), "r"(b0), "r"(b1))

// ---------------- BN fold ----------------
__global__ void bn_prep_kernel(
    const float* __restrict__ g1, const float* __restrict__ b1,
    const float* __restrict__ m1, const float* __restrict__ v1,
    const float* __restrict__ g2, const float* __restrict__ b2,
    const float* __restrict__ m2, const float* __restrict__ v2,
    const float* __restrict__ gd, const float* __restrict__ bd,
    const float* __restrict__ md, const float* __restrict__ vd)
{
    int c = threadIdx.x;
    if (c < COUT) {
        float i1 = g1[c] * __frsqrt_rn(v1[c] + BN_EPS);
        g_scale[c] = i1;             g_bias[c] = b1[c] - m1[c] * i1;
        float i2 = g2[c] * __frsqrt_rn(v2[c] + BN_EPS);
        g_scale[COUT + c] = i2;      g_bias[COUT + c] = b2[c] - m2[c] * i2;
        float id_ = gd[c] * __frsqrt_rn(vd[c] + BN_EPS);
        g_scale[2*COUT + c] = id_;   g_bias[2*COUT + c] = bd[c] - md[c] * id_;
        g_b2d[c] = (b2[c] - m2[c] * i2) + (bd[c] - md[c] * id_);
    }
}

// ---------------- weight pack: conv2 + ds ----------------
// Fragment (nt, lane) stored at uint2 offset (nt>>2)*128 + lane*4 + (nt&3)
// so warp ng reads its 4 j-fragments per lane as one contiguous 32B run.
__global__ void wpack_kernel(const float* __restrict__ w2, const float* __restrict__ wd)
{
    int id = blockIdx.x * 256 + threadIdx.x;
    if (id >= NKS * 1024) return;
    int lane = id & 31, nt = (id >> 5) & 31, k = id >> 10;
    int co = nt * 8 + (lane >> 2);
    uint32_t out[2];
#pragma unroll
    for (int r = 0; r < 2; r++) {
        int kk = (lane & 3) * 2 + r * 8;
        float w0, w1; int s;
        if (k < 432) {
            int kc = k / 27, rr = k % 27, tap = rr / 3; s = rr % 3;
            int ci = kc * 16 + kk;
            float sc = g_scale[COUT + co];
            w0 = w2[((size_t)co * COUT + ci)     * 9 + tap] * sc;
            w1 = w2[((size_t)co * COUT + ci + 1) * 9 + tap] * sc;
        } else {
            int d = k - 432, kc = d / 3; s = d % 3;
            int ci = kc * 16 + kk;
            float sc = g_scale[2*COUT + co];
            w0 = wd[co * CIN + ci] * sc;
            w1 = wd[co * CIN + ci + 1] * sc;
        }
        out[r] = pk_bf16(split_term(w0, s), split_term(w1, s));
    }
    ((uint2*)g_wpack)[(size_t)k * 1024 + (nt >> 2) * 128 + lane * 4 + (nt & 3)]
        = make_uint2(out[0], out[1]);
}

// ---------------- conv1 (3x3 s2 p1) + BN -> g_u1 (FFMA, proven) ----------------
__global__ __launch_bounds__(256) void conv1_kernel(
    const float* __restrict__ x, const float* __restrict__ w1)
{
    __shared__ float sx[4 * 9 * 60];
    __shared__ float sw[4 * 9 * 64];

    const int n   = blockIdx.z;
    const int co0 = blockIdx.y * 64;
    const int h0  = blockIdx.x * 4;
    const int tid = threadIdx.x;
    const int cog = tid >> 4;
    const int pxg = tid & 15;
    const int h_local = pxg >> 2;
    const int w_base  = (pxg & 3) * 7;

    float acc[4][7];
#pragma unroll
    for (int a = 0; a < 4; a++)
#pragma unroll
        for (int j = 0; j < 7; j++) acc[a][j] = 0.f;

    const float* xn = x + (size_t)n * CIN * HIN * HIN;

    for (int ci0 = 0; ci0 < CIN; ci0 += 4) {
        __syncthreads();
        for (int idx = tid; idx < 4 * 9 * 60; idx += 256) {
            int c  = idx % 60;
            int i  = (idx / 60) % 9;
            int ci = idx / 540;
            int r  = 2 * h0 - 1 + i;
            int gc = c - 1;
            float v = 0.f;
            if (c < 57 && r >= 0 && r < HIN && gc >= 0 && gc < HIN)
                v = xn[(size_t)(ci0 + ci) * (HIN * HIN) + r * HIN + gc];
            sx[idx] = v;
        }
        {
            int col = tid >> 2;
            int ci  = tid & 3;
            const float* src = &w1[((size_t)(co0 + col) * CIN + ci0 + ci) * 9];
#pragma unroll
            for (int kq = 0; kq < 9; kq++) sw[(ci * 9 + kq) * 64 + col] = src[kq];
        }
        __syncthreads();

#pragma unroll 2
        for (int ci = 0; ci < 4; ci++) {
#pragma unroll
            for (int kh = 0; kh < 3; kh++) {
                const float* row = &sx[(ci * 9 + 2 * h_local + kh) * 60 + 2 * w_base];
                float r[15];
#pragma unroll
                for (int m = 0; m < 15; m++) r[m] = row[m];
#pragma unroll
                for (int kw = 0; kw < 3; kw++) {
                    float4 a = *(const float4*)&sw[(ci * 9 + kh * 3 + kw) * 64 + cog * 4];
#pragma unroll
                    for (int j = 0; j < 7; j++) {
                        float bb = r[2 * j + kw];
                        acc[0][j] += a.x * bb; acc[1][j] += a.y * bb;
                        acc[2][j] += a.z * bb; acc[3][j] += a.w * bb;
                    }
                }
            }
        }
    }

#pragma unroll
    for (int cc = 0; cc < 4; cc++) {
        int co = co0 + cog * 4 + cc;
        float s1 = g_scale[co], b1v = g_bias[co];
        size_t base = ((size_t)n * COUT + co) * PP + (h0 + h_local) * P + w_base;
#pragma unroll
        for (int j = 0; j < 7; j++)
            g_u1[base + j] = acc[cc][j] * s1 + b1v;
    }
}

// ---------------- LIF ----------------
__device__ __forceinline__ void lif_scan(const float4* __restrict__ in4,
                                         float4* __restrict__ out4, int idx)
{
    const int per_b = COUT * PP / 4;
    int b = idx / per_b;
    int r = idx - b * per_b;
    size_t base = (size_t)b * T_ * per_b + r;
    float vx = 0.f, vy = 0.f, vz = 0.f, vw = 0.f;
#pragma unroll
    for (int t = 0; t < T_; t++) {
        size_t off = base + (size_t)t * per_b;
        float4 u = in4[off];
        float4 s;
        vx += (u.x - vx) * 0.5f; s.x = vx > 1.0f ? 1.0f : 0.0f; if (vx > 1.0f) vx = 0.f;
        vy += (u.y - vy) * 0.5f; s.y = vy > 1.0f ? 1.0f : 0.0f; if (vy > 1.0f) vy = 0.f;
        vz += (u.z - vz) * 0.5f; s.z = vz > 1.0f ? 1.0f : 0.0f; if (vz > 1.0f) vz = 0.f;
        vw += (u.w - vw) * 0.5f; s.w = vw > 1.0f ? 1.0f : 0.0f; if (vw > 1.0f) vw = 0.f;
        out4[off] = s;
    }
}
__global__ __launch_bounds__(256) void lif1_kernel(){
    lif_scan((const float4*)g_u1, (float4*)g_s1, blockIdx.x * 256 + threadIdx.x);
}
__global__ __launch_bounds__(256) void lif2_kernel(float* __restrict__ out){
    lif_scan((const float4*)g_u2, (float4*)out, blockIdx.x * 256 + threadIdx.x);
}

// ---------------- conv2 (3x3 s1 p1) + ds(1x1 s2) + biases -> g_u2 (mma.sync) ----------------
// Retiled: warp = M64 x N32. mg = wid&1 selects px 0-63 / 64-127 (rows 2mg,2mg+1);
// ng = wid>>1 selects co block ng*32. B per warp: 1KB/kstep via 2x LDS.128.
__global__ __launch_bounds__(512, 1) void conv2_mma_kernel(const float* __restrict__ x)
{
    __shared__ uint4 bufB[2][512];
    __shared__ __align__(16) unsigned short patch[6 * 36 * 16];  // ds aliases [128][16]
    __shared__ float sbias[256];

    const int tid = threadIdx.x, lane = tid & 31, wid = tid >> 5;
    const int mg = wid & 1, ng = wid >> 1;
    const int n = blockIdx.y, h0 = blockIdx.x * 4;

    if (tid < 256) sbias[tid] = g_b2d[tid];
    bufB[0][tid] = ((const uint4*)g_wpack)[tid];

    const int wl    = ((lane >> 3) & 1) * 8 + (lane & 7);
    const int khalf = lane >> 4;
    const uint32_t pbase = smem_u32(patch);
    // tile t (0..3): px = mg*64 + t*16 -> patch row 2mg+(t>>1), col base (t&1)*16
    uint32_t cbase[4], dbase[4];
#pragma unroll
    for (int t = 0; t < 4; t++) {
        cbase[t] = pbase + (uint32_t)((((2 * mg + (t >> 1)) * 36) + (t & 1) * 16 + wl) * 32
                                      + khalf * 16);
        dbase[t] = pbase + (uint32_t)((mg * 64 + t * 16 + wl) * 32 + khalf * 16);
    }

    float acc[4][4][4];
#pragma unroll
    for (int t = 0; t < 4; t++)
#pragma unroll
        for (int j = 0; j < 4; j++)
#pragma unroll
            for (int q = 0; q < 4; q++) acc[t][j][q] = 0.f;

    uint32_t a[4][4];
    const float* s1n = g_s1 + (size_t)n * COUT * PP;
    const float* xn  = x    + (size_t)n * CIN * HIN * HIN;

    for (int k = 0; k < NKS; k++) {
        __syncthreads();
        const bool isds = (k >= 432);
        const int  kk   = isds ? (k - 432) : k;
        const bool refill = isds ? (kk % 3 == 0) : (k % 27 == 0);

        if (refill) {
            if (!isds) {
                int kc = k / 27;
                for (int i = tid; i < 1728; i += 512) {
                    int ci2 = i & 7, col = (i >> 3) % 36, row = i / 288;
                    int ir = h0 - 1 + row, ic = col - 1;
                    uint32_t v = 0;
                    if (col < 34 && (unsigned)ir < 28u && (unsigned)ic < 28u) {
                        const float* p = s1n + (size_t)(kc * 16 + ci2 * 2) * PP + ir * P + ic;
                        v = pk_bf16(p[0], p[PP]);
                    }
                    ((uint32_t*)patch)[(row * 36 + col) * 8 + ci2] = v;
                }
            } else {
                int kc = kk / 3;
                for (int i = tid; i < 1024; i += 512) {
                    int ci2 = i & 7, p = i >> 3;
                    int hh = h0 + (p >> 5), w = p & 31;
                    int ic = 2 * w; if (ic > 54) ic = 54;
                    const float* pp = xn + (size_t)(kc * 16 + ci2 * 2) * (HIN * HIN)
                                    + (2 * hh) * HIN + ic;
                    ((uint32_t*)patch)[p * 8 + ci2] = pk_bf16(pp[0], pp[HIN * HIN]);
                }
            }
        }
        if (k + 1 < NKS)
            bufB[(k + 1) & 1][tid] = ((const uint4*)g_wpack)[(size_t)(k + 1) * 512 + tid];
        if (refill) __syncthreads();

        if ((isds ? (kk % 3) : (k % 3)) == 0) {
            if (!isds) {
                int rr = k % 27, tap = rr / 3, kh = tap / 3, kw = tap % 3;
                uint32_t off = (uint32_t)((kh * 36 + kw) * 32);
#pragma unroll
                for (int t = 0; t < 4; t++) LDM4(a[t], cbase[t] + off);
            } else {
#pragma unroll
                for (int t = 0; t < 4; t++) LDM4(a[t], dbase[t]);
            }
        }

        const uint4* bb4 = (const uint4*)bufB[k & 1] + ng * 64 + lane * 2;
        uint4 q0 = bb4[0], q1 = bb4[1];   // j0,j1 | j2,j3
#pragma unroll
        for (int t = 0; t < 4; t++) {
            MMA16816(acc[t][0], a[t], q0.x, q0.y);
            MMA16816(acc[t][1], a[t], q0.z, q0.w);
            MMA16816(acc[t][2], a[t], q1.x, q1.y);
            MMA16816(acc[t][3], a[t], q1.z, q1.w);
        }
    }

    // ---- epilogue ----
    const int rw = lane >> 2, cb = (lane & 3) * 2;
#pragma unroll
    for (int t = 0; t < 4; t++) {
        int h = h0 + 2 * mg + (t >> 1);
        int w  = (t & 1) * 16 + rw;        // always < 28
        int w8 = w + 8;                    // may exceed 27 when t&1
#pragma unroll
        for (int j = 0; j < 4; j++) {
            int co = ng * 32 + j * 8 + cb;
            float b0 = sbias[co], b1 = sbias[co + 1];
            size_t base0 = ((size_t)n * COUT + co) * PP + (size_t)h * P;
            size_t base1 = base0 + PP;
            g_u2[base0 + w] = acc[t][j][0] + b0;
            g_u2[base1 + w] = acc[t][j][1] + b1;
            if (w8 < P) {
                g_u2[base0 + w8] = acc[t][j][2] + b0;
                g_u2[base1 + w8] = acc[t][j][3] + b1;
            }
        }
    }
}

// ---------------- launch ----------------
extern "C" void kernel_launch(void* const* d_in, const int* in_sizes, int n_in,
                              void* d_out, int out_size)
{
    (void)in_sizes; (void)n_in; (void)out_size;
    const float* x  = (const float*)d_in[0];
    const float* w1 = (const float*)d_in[1];
    const float* w2 = (const float*)d_in[2];
    const float* wd = (const float*)d_in[3];

    bn_prep_kernel<<<1, 256>>>(
        (const float*)d_in[4],  (const float*)d_in[5],
        (const float*)d_in[6],  (const float*)d_in[7],
        (const float*)d_in[8],  (const float*)d_in[9],
        (const float*)d_in[10], (const float*)d_in[11],
        (const float*)d_in[12], (const float*)d_in[13],
        (const float*)d_in[14], (const float*)d_in[15]);

    wpack_kernel<<<(NKS * 1024 + 255) / 256, 256>>>(w2, wd);

    conv1_kernel<<<dim3(7, 4, NIMG), 256>>>(x, w1);

    const int lif_threads = B_ * COUT * PP / 4;
    lif1_kernel<<<lif_threads / 256, 256>>>();

    conv2_mma_kernel<<<dim3(7, NIMG), 512>>>(x);

    lif2_kernel<<<lif_threads / 256, 256>>>((float*)d_out);
}

// round 17
// speedup vs baseline: 1.0980x; 1.0980x over previous
#include <cuda_runtime.h>
#include <cuda_bf16.h>
#include <stdint.h>

#define B_    16
#define T_    8
#define NIMG  128
#define CIN   128
#define COUT  256
#define HIN   56
#define P     28
#define PP    784
#define BN_EPS 1e-5f

#define NKS   456          // conv2: 432 + 24 ds k-steps

// ---------------- device scratch ----------------
__device__ float g_u1[(size_t)NIMG * COUT * PP];
__device__ float g_s1[(size_t)NIMG * COUT * PP];
__device__ float g_u2[(size_t)NIMG * COUT * PP];
__device__ float g_scale[3 * COUT];
__device__ float g_bias[3 * COUT];
__device__ float g_b2d[COUT];
// B fragments: [kstep][nt 32][lane 32] uint2 (uint2 = 2x bf16-pair along k)
__device__ __align__(16) uint32_t g_wpack[(size_t)NKS * 2048];

// ---------------- helpers ----------------
__device__ __forceinline__ uint32_t smem_u32(const void* p){
    uint32_t a;
    asm("{ .reg .u64 t; cvta.to.shared.u64 t, %1; cvt.u32.u64 %0, t; }" : "=r"(a) : "l"(p));
    return a;
}
__device__ __forceinline__ uint32_t pk_bf16(float a, float b){
    return (uint32_t)__bfloat16_as_ushort(__float2bfloat16(a))
         | ((uint32_t)__bfloat16_as_ushort(__float2bfloat16(b)) << 16);
}
__device__ __forceinline__ float split_term(float w, int s){
    float a = __bfloat162float(__float2bfloat16(w));
    if (s == 0) return a;
    float r = w - a;
    float b = __bfloat162float(__float2bfloat16(r));
    if (s == 1) return b;
    return r - b;
}

#define LDM4(a, ad) asm volatile( \
    "ldmatrix.sync.aligned.m8n8.x4.shared.b16 {%0,%1,%2,%3}, [%4];" \
    : "=r"((a)[0]), "=r"((a)[1]), "=r"((a)[2]), "=r"((a)[3]) : "r"(ad))

#define MMA16816(c, a, b0, b1) asm volatile( \
    "mma.sync.aligned.m16n8k16.row.col.f32.bf16.bf16.f32 " \
    "{%0,%1,%2,%3}, {%4,%5,%6,%7}, {%8,%9}, {%0,%1,%2,%3};" \
    : "+f"((c)[0]), "+f"((c)[1]), "+f"((c)[2]), "+f"((c)[3]) \
    : "r"((a)[0]), "r"((a)[1]), "r"((a)[2]), "r"((a)[3]), "r"(b0), "r"(b1))

#define CP_ASYNC16(saddr, gptr) asm volatile( \
    "cp.async.cg.shared.global [%0], [%1], 16;" :: "r"(saddr), "l"(gptr) : "memory")
#define CP_COMMIT() asm volatile("cp.async.commit_group;" ::: "memory")
#define CP_WAIT1()  asm volatile("cp.async.wait_group 1;" ::: "memory")
#define CP_WAIT0()  asm volatile("cp.async.wait_group 0;" ::: "memory")

// ---------------- BN fold ----------------
__global__ void bn_prep_kernel(
    const float* __restrict__ g1, const float* __restrict__ b1,
    const float* __restrict__ m1, const float* __restrict__ v1,
    const float* __restrict__ g2, const float* __restrict__ b2,
    const float* __restrict__ m2, const float* __restrict__ v2,
    const float* __restrict__ gd, const float* __restrict__ bd,
    const float* __restrict__ md, const float* __restrict__ vd)
{
    int c = threadIdx.x;
    if (c < COUT) {
        float i1 = g1[c] * __frsqrt_rn(v1[c] + BN_EPS);
        g_scale[c] = i1;             g_bias[c] = b1[c] - m1[c] * i1;
        float i2 = g2[c] * __frsqrt_rn(v2[c] + BN_EPS);
        g_scale[COUT + c] = i2;      g_bias[COUT + c] = b2[c] - m2[c] * i2;
        float id_ = gd[c] * __frsqrt_rn(vd[c] + BN_EPS);
        g_scale[2*COUT + c] = id_;   g_bias[2*COUT + c] = bd[c] - md[c] * id_;
        g_b2d[c] = (b2[c] - m2[c] * i2) + (bd[c] - md[c] * id_);
    }
}

// ---------------- weight pack: conv2 + ds (R8 layout) ----------------
__global__ void wpack_kernel(const float* __restrict__ w2, const float* __restrict__ wd)
{
    int id = blockIdx.x * 256 + threadIdx.x;
    if (id >= NKS * 1024) return;
    int lane = id & 31, nt = (id >> 5) & 31, k = id >> 10;
    int co = nt * 8 + (lane >> 2);
    uint32_t out[2];
#pragma unroll
    for (int r = 0; r < 2; r++) {
        int kk = (lane & 3) * 2 + r * 8;
        float w0, w1; int s;
        if (k < 432) {
            int kc = k / 27, rr = k % 27, tap = rr / 3; s = rr % 3;
            int ci = kc * 16 + kk;
            float sc = g_scale[COUT + co];
            w0 = w2[((size_t)co * COUT + ci)     * 9 + tap] * sc;
            w1 = w2[((size_t)co * COUT + ci + 1) * 9 + tap] * sc;
        } else {
            int d = k - 432, kc = d / 3; s = d % 3;
            int ci = kc * 16 + kk;
            float sc = g_scale[2*COUT + co];
            w0 = wd[co * CIN + ci] * sc;
            w1 = wd[co * CIN + ci + 1] * sc;
        }
        out[r] = pk_bf16(split_term(w0, s), split_term(w1, s));
    }
    ((uint2*)g_wpack)[(size_t)(k * 32 + nt) * 32 + lane] = make_uint2(out[0], out[1]);
}

// ---------------- conv1 (3x3 s2 p1) + BN -> g_u1 (FFMA, proven) ----------------
__global__ __launch_bounds__(256) void conv1_kernel(
    const float* __restrict__ x, const float* __restrict__ w1)
{
    __shared__ float sx[4 * 9 * 60];
    __shared__ float sw[4 * 9 * 64];

    const int n   = blockIdx.z;
    const int co0 = blockIdx.y * 64;
    const int h0  = blockIdx.x * 4;
    const int tid = threadIdx.x;
    const int cog = tid >> 4;
    const int pxg = tid & 15;
    const int h_local = pxg >> 2;
    const int w_base  = (pxg & 3) * 7;

    float acc[4][7];
#pragma unroll
    for (int a = 0; a < 4; a++)
#pragma unroll
        for (int j = 0; j < 7; j++) acc[a][j] = 0.f;

    const float* xn = x + (size_t)n * CIN * HIN * HIN;

    for (int ci0 = 0; ci0 < CIN; ci0 += 4) {
        __syncthreads();
        for (int idx = tid; idx < 4 * 9 * 60; idx += 256) {
            int c  = idx % 60;
            int i  = (idx / 60) % 9;
            int ci = idx / 540;
            int r  = 2 * h0 - 1 + i;
            int gc = c - 1;
            float v = 0.f;
            if (c < 57 && r >= 0 && r < HIN && gc >= 0 && gc < HIN)
                v = xn[(size_t)(ci0 + ci) * (HIN * HIN) + r * HIN + gc];
            sx[idx] = v;
        }
        {
            int col = tid >> 2;
            int ci  = tid & 3;
            const float* src = &w1[((size_t)(co0 + col) * CIN + ci0 + ci) * 9];
#pragma unroll
            for (int kq = 0; kq < 9; kq++) sw[(ci * 9 + kq) * 64 + col] = src[kq];
        }
        __syncthreads();

#pragma unroll 2
        for (int ci = 0; ci < 4; ci++) {
#pragma unroll
            for (int kh = 0; kh < 3; kh++) {
                const float* row = &sx[(ci * 9 + 2 * h_local + kh) * 60 + 2 * w_base];
                float r[15];
#pragma unroll
                for (int m = 0; m < 15; m++) r[m] = row[m];
#pragma unroll
                for (int kw = 0; kw < 3; kw++) {
                    float4 a = *(const float4*)&sw[(ci * 9 + kh * 3 + kw) * 64 + cog * 4];
#pragma unroll
                    for (int j = 0; j < 7; j++) {
                        float bb = r[2 * j + kw];
                        acc[0][j] += a.x * bb; acc[1][j] += a.y * bb;
                        acc[2][j] += a.z * bb; acc[3][j] += a.w * bb;
                    }
                }
            }
        }
    }

#pragma unroll
    for (int cc = 0; cc < 4; cc++) {
        int co = co0 + cog * 4 + cc;
        float s1 = g_scale[co], b1v = g_bias[co];
        size_t base = ((size_t)n * COUT + co) * PP + (h0 + h_local) * P + w_base;
#pragma unroll
        for (int j = 0; j < 7; j++)
            g_u1[base + j] = acc[cc][j] * s1 + b1v;
    }
}

// ---------------- LIF ----------------
__device__ __forceinline__ void lif_scan(const float4* __restrict__ in4,
                                         float4* __restrict__ out4, int idx)
{
    const int per_b = COUT * PP / 4;
    int b = idx / per_b;
    int r = idx - b * per_b;
    size_t base = (size_t)b * T_ * per_b + r;
    float vx = 0.f, vy = 0.f, vz = 0.f, vw = 0.f;
#pragma unroll
    for (int t = 0; t < T_; t++) {
        size_t off = base + (size_t)t * per_b;
        float4 u = in4[off];
        float4 s;
        vx += (u.x - vx) * 0.5f; s.x = vx > 1.0f ? 1.0f : 0.0f; if (vx > 1.0f) vx = 0.f;
        vy += (u.y - vy) * 0.5f; s.y = vy > 1.0f ? 1.0f : 0.0f; if (vy > 1.0f) vy = 0.f;
        vz += (u.z - vz) * 0.5f; s.z = vz > 1.0f ? 1.0f : 0.0f; if (vz > 1.0f) vz = 0.f;
        vw += (u.w - vw) * 0.5f; s.w = vw > 1.0f ? 1.0f : 0.0f; if (vw > 1.0f) vw = 0.f;
        out4[off] = s;
    }
}
__global__ __launch_bounds__(256) void lif1_kernel(){
    lif_scan((const float4*)g_u1, (float4*)g_s1, blockIdx.x * 256 + threadIdx.x);
}
__global__ __launch_bounds__(256) void lif2_kernel(float* __restrict__ out){
    lif_scan((const float4*)g_u2, (float4*)out, blockIdx.x * 256 + threadIdx.x);
}

// ---------------- conv2 (3x3 s1 p1) + ds(1x1 s2) + biases -> g_u2 (mma.sync) ----------------
// R8 tiling (warp = M32 x N64); B staged via cp.async (no register roundtrip):
//   sync1 -> issue async copy k+1 -> [patch refill] -> wait_group -> sync2 -> consume k
__global__ __launch_bounds__(512, 1) void conv2_mma_kernel(const float* __restrict__ x)
{
    __shared__ uint4 bufB[2][512];
    __shared__ __align__(16) unsigned short patch[6 * 36 * 16];  // ds aliases [128][16]
    __shared__ float sbias[256];

    const int tid = threadIdx.x, lane = tid & 31, wid = tid >> 5;
    const int mg = wid & 3, ng = wid >> 2;
    const int n = blockIdx.y, h0 = blockIdx.x * 4;

    if (tid < 256) sbias[tid] = g_b2d[tid];

    const uint32_t bAddr[2] = { smem_u32(&bufB[0][tid]), smem_u32(&bufB[1][tid]) };
    const uint4* Wg = (const uint4*)g_wpack + tid;        // + k*512

    // prologue: async copy for kstep 0
    CP_ASYNC16(bAddr[0], Wg);
    CP_COMMIT();

    const int wl    = ((lane >> 3) & 1) * 8 + (lane & 7);
    const int khalf = lane >> 4;
    const uint32_t pbase = smem_u32(patch);
    uint32_t cbase[2], dbase[2];
    cbase[0] = pbase + (uint32_t)((mg * 36 + wl) * 32 + khalf * 16);
    cbase[1] = cbase[0] + 16 * 32;
    dbase[0] = pbase + (uint32_t)((mg * 32 + wl) * 32 + khalf * 16);
    dbase[1] = dbase[0] + 16 * 32;

    float acc[2][8][4];
#pragma unroll
    for (int t = 0; t < 2; t++)
#pragma unroll
        for (int j = 0; j < 8; j++)
#pragma unroll
            for (int q = 0; q < 4; q++) acc[t][j][q] = 0.f;

    uint32_t a[2][4];
    const float* s1n = g_s1 + (size_t)n * COUT * PP;
    const float* xn  = x    + (size_t)n * CIN * HIN * HIN;

    for (int k = 0; k < NKS; k++) {
        const bool isds = (k >= 432);
        const int  kk   = isds ? (k - 432) : k;
        const bool refill = isds ? (kk % 3 == 0) : (k % 27 == 0);

        __syncthreads();   // all warps done consuming bufB[(k+1)&1] (iter k-1) and prev patch

        if (k + 1 < NKS) {
            CP_ASYNC16(bAddr[(k + 1) & 1], Wg + (size_t)(k + 1) * 512);
            CP_COMMIT();
        }

        if (refill) {
            if (!isds) {
                int kc = k / 27;
                for (int i = tid; i < 1728; i += 512) {
                    int ci2 = i & 7, col = (i >> 3) % 36, row = i / 288;
                    int ir = h0 - 1 + row, ic = col - 1;
                    uint32_t v = 0;
                    if (col < 34 && (unsigned)ir < 28u && (unsigned)ic < 28u) {
                        const float* p = s1n + (size_t)(kc * 16 + ci2 * 2) * PP + ir * P + ic;
                        v = pk_bf16(p[0], p[PP]);
                    }
                    ((uint32_t*)patch)[(row * 36 + col) * 8 + ci2] = v;
                }
            } else {
                int kc = kk / 3;
                for (int i = tid; i < 1024; i += 512) {
                    int ci2 = i & 7, p = i >> 3;
                    int hh = h0 + (p >> 5), w = p & 31;
                    int ic = 2 * w; if (ic > 54) ic = 54;
                    const float* pp = xn + (size_t)(kc * 16 + ci2 * 2) * (HIN * HIN)
                                    + (2 * hh) * HIN + ic;
                    ((uint32_t*)patch)[p * 8 + ci2] = pk_bf16(pp[0], pp[HIN * HIN]);
                }
            }
        }

        if (k + 1 < NKS) { CP_WAIT1(); } else { CP_WAIT0(); }   // group k complete
        __syncthreads();   // bufB[k&1] + patch visible to all warps

        if ((isds ? (kk % 3) : (k % 3)) == 0) {
            if (!isds) {
                int rr = k % 27, tap = rr / 3, kh = tap / 3, kw = tap % 3;
                uint32_t off = (uint32_t)((kh * 36 + kw) * 32);
                LDM4(a[0], cbase[0] + off);
                LDM4(a[1], cbase[1] + off);
            } else {
                LDM4(a[0], dbase[0]);
                LDM4(a[1], dbase[1]);
            }
        }

        const uint2* bb = (const uint2*)bufB[k & 1] + ng * 256 + lane;
#pragma unroll
        for (int j = 0; j < 8; j++) {
            uint2 bf = bb[j * 32];
            MMA16816(acc[0][j], a[0], bf.x, bf.y);
            MMA16816(acc[1][j], a[1], bf.x, bf.y);
        }
    }

    // ---- epilogue: acc + bias -> g_u2 (NCHW) ----
    const int rw = lane >> 2, cb = (lane & 3) * 2, h = h0 + mg;
#pragma unroll
    for (int t = 0; t < 2; t++) {
        int w = t * 16 + rw;
#pragma unroll
        for (int j = 0; j < 8; j++) {
            int co = ng * 64 + j * 8 + cb;
            float b0 = sbias[co], b1 = sbias[co + 1];
            size_t base0 = ((size_t)n * COUT + co) * PP + (size_t)h * P;
            size_t base1 = base0 + PP;
            if (w < P) {
                g_u2[base0 + w] = acc[t][j][0] + b0;
                g_u2[base1 + w] = acc[t][j][1] + b1;
            }
            int w8 = w + 8;
            if (w8 < P) {
                g_u2[base0 + w8] = acc[t][j][2] + b0;
                g_u2[base1 + w8] = acc[t][j][3] + b1;
            }
        }
    }
}

// ---------------- launch ----------------
extern "C" void kernel_launch(void* const* d_in, const int* in_sizes, int n_in,
                              void* d_out, int out_size)
{
    (void)in_sizes; (void)n_in; (void)out_size;
    const float* x  = (const float*)d_in[0];
    const float* w1 = (const float*)d_in[1];
    const float* w2 = (const float*)d_in[2];
    const float* wd = (const float*)d_in[3];

    bn_prep_kernel<<<1, 256>>>(
        (const float*)d_in[4],  (const float*)d_in[5],
        (const float*)d_in[6],  (const float*)d_in[7],
        (const float*)d_in[8],  (const float*)d_in[9],
        (const float*)d_in[10], (const float*)d_in[11],
        (const float*)d_in[12], (const float*)d_in[13],
        (const float*)d_in[14], (const float*)d_in[15]);

    wpack_kernel<<<(NKS * 1024 + 255) / 256, 256>>>(w2, wd);

    conv1_kernel<<<dim3(7, 4, NIMG), 256>>>(x, w1);

    const int lif_threads = B_ * COUT * PP / 4;
    lif1_kernel<<<lif_threads / 256, 256>>>();

    conv2_mma_kernel<<<dim3(7, NIMG), 512>>>(x);

    lif2_kernel<<<lif_threads / 256, 256>>>((float*)d_out);
}